// round 1
// baseline (speedup 1.0000x reference)
#include <cuda_runtime.h>

#define NQ    12
#define DEPTH 6
#define TPB   128

typedef unsigned int u32;

// ---------------------------------------------------------------------------
// Reference index convention: wire q <-> flat-index bit (11-q) (big-endian).
// CNOT ring: for q in 0..11: CNOT(wire q, wire q+1 mod 12)
//   => in bit space, gate g: control bit c=11-g, target bit t=(c+11)%12.
// State map: psi'[b] = psi[C(b)], C(b) = b ^ ((b>>c & 1) << t).
// After full ring: psi_final = psi0 ∘ C_g1 ∘ C_g2 ∘ ... ∘ C_g12
//   F(b)    : apply LAST gate's map innermost  (g=11 first)
//   Finv(b) : apply gates in application order (g=0 first)
// Storage invariant: sv[Q_d(b)] holds logical amplitude b at layer d, Q_d=F^d.
// ---------------------------------------------------------------------------
__host__ __device__ constexpr u32 Fmap(u32 b) {
    for (int g = 11; g >= 0; --g) {
        int c = 11 - g, t = (c + 11) % NQ;
        b ^= ((b >> c) & 1u) << t;
    }
    return b;
}
__host__ __device__ constexpr u32 Finvmap(u32 b) {
    for (int g = 0; g < NQ; ++g) {
        int c = 11 - g, t = (c + 11) % NQ;
        b ^= ((b >> c) & 1u) << t;
    }
    return b;
}
// GF(2)-linear smem anti-bank-conflict swizzle (composes into the mask tables)
__host__ __device__ constexpr u32 swz(u32 x) { return x ^ ((x >> 5) & 31u); }

struct Tabs {
    u32 q[DEPTH][NQ];  // swizzled columns of Q_d = F^d
    u32 finv[NQ];      // columns of F^{-1} (logical space, for final weights)
};
__host__ __device__ constexpr Tabs mk_tabs() {
    Tabs t{};
    u32 raw[NQ] = {};
    for (int j = 0; j < NQ; ++j) { raw[j] = 1u << j; t.q[0][j] = swz(raw[j]); }
    for (int d = 1; d < DEPTH; ++d)
        for (int j = 0; j < NQ; ++j) { raw[j] = Fmap(raw[j]); t.q[d][j] = swz(raw[j]); }
    for (int j = 0; j < NQ; ++j) t.finv[j] = Finvmap(1u << j);
    return t;
}
__constant__ Tabs TAB = mk_tabs();

// Pass p owns 5 bit-directions (c-bit k <-> logical bit DIRS[p][k]);
// gates applied on the first 4 owned directions; the 7 filler bits come
// from the thread id in FILL[p] order.
__constant__ int DIRS[3][5] = {{0,1,2,3,4},{4,5,6,7,8},{8,9,10,11,0}};
__constant__ int FILL[3][7] = {{5,6,7,8,9,10,11},{0,1,2,3,9,10,11},{1,2,3,4,5,6,7}};

__global__ void __launch_bounds__(TPB, 4)
qsim_kernel(const float* __restrict__ inp, const float* __restrict__ wp,
            float* __restrict__ out)
{
    __shared__ float2 sv[1 << NQ];            // 32 KB state
    __shared__ float2 gms[DEPTH * NQ * 4];    // 2.25 KB gate matrices (by bit m)
    __shared__ float  csm[NQ * 2];            // encode cos/sin per bit
    __shared__ float  red[TPB / 32];

    const int t   = threadIdx.x;
    const int bid = blockIdx.x;

    // ---- per-block prep: gate matrices (shared weights) + encode factors ----
    if (t < DEPTH * NQ) {
        int d = t / NQ, m = t % NQ;          // m = bit index, wire = 11-m
        int wo = (d * NQ + (11 - m)) * 3;
        float phi = wp[wo + 0], th = wp[wo + 1], om = wp[wo + 2];
        float st, ct; sincosf(0.5f * th, &st, &ct);
        float sa, ca; sincosf(0.5f * (phi + om), &sa, &ca);
        float sb, cb; sincosf(0.5f * (phi - om), &sb, &cb);
        // Rot = [[e^{-ia}c, -e^{ib}s],[e^{-ib}s, e^{ia}c]]
        gms[t * 4 + 0] = make_float2( ct * ca, -ct * sa);   // m00
        gms[t * 4 + 1] = make_float2(-st * cb, -st * sb);   // m01
        gms[t * 4 + 2] = make_float2( st * cb, -st * sb);   // m10
        gms[t * 4 + 3] = make_float2( ct * ca,  ct * sa);   // m11
    }
    if (t < NQ) {
        float x = inp[bid * NQ + (11 - t)];   // bit t <- wire 11-t
        float s, c; sincosf(0.5f * x, &s, &c);
        csm[t * 2 + 0] = c; csm[t * 2 + 1] = s;
    }
    __syncthreads();

    float acc = 0.f;

    for (int d = 0; d < DEPTH; ++d) {
        const u32* qc = TAB.q[d];
        for (int p = 0; p < 3; ++p) {
            // physical (swizzled) base address + owned-direction masks
            u32 pb = 0;
            #pragma unroll
            for (int j = 0; j < 7; ++j)
                if ((t >> j) & 1) pb ^= qc[FILL[p][j]];
            u32 qd[5];
            #pragma unroll
            for (int k = 0; k < 5; ++k) qd[k] = qc[DIRS[p][k]];

            float2 s[32];
            if (d == 0 && p == 0) {
                // ---- angle encoding: psi[b] = prod_m (b_m ? sin : cos) ----
                float f = csm[5 * 2 + (t & 1)];
                #pragma unroll
                for (int j = 1; j < 7; ++j) f *= csm[(5 + j) * 2 + ((t >> j) & 1)];
                float v[32]; v[0] = f;
                #pragma unroll
                for (int j = 0; j < 5; ++j) {
                    #pragma unroll
                    for (int k = 0; k < (1 << j); ++k) {
                        float lo = v[k];
                        v[k]            = lo * csm[j * 2 + 0];
                        v[k + (1 << j)] = lo * csm[j * 2 + 1];
                    }
                }
                #pragma unroll
                for (int c = 0; c < 32; ++c) s[c] = make_float2(v[c], 0.f);
            } else {
                #pragma unroll
                for (int c = 0; c < 32; ++c) {
                    u32 a = pb;
                    if (c & 1)  a ^= qd[0];
                    if (c & 2)  a ^= qd[1];
                    if (c & 4)  a ^= qd[2];
                    if (c & 8)  a ^= qd[3];
                    if (c & 16) a ^= qd[4];
                    s[c] = sv[a];
                }
            }

            // ---- 4 register-resident gates on owned bits p*4 .. p*4+3 ----
            const float2* g4 = &gms[(d * NQ + p * 4) * 4];
            #pragma unroll
            for (int g = 0; g < 4; ++g) {
                float2 m00 = g4[4*g+0], m01 = g4[4*g+1], m10 = g4[4*g+2], m11 = g4[4*g+3];
                #pragma unroll
                for (int c = 0; c < 32; ++c) {
                    if (!((c >> g) & 1)) {
                        float2 a0 = s[c], a1 = s[c | (1 << g)];
                        float2 n0, n1;
                        n0.x = fmaf(m00.x, a0.x, fmaf(-m00.y, a0.y, fmaf(m01.x, a1.x, -m01.y * a1.y)));
                        n0.y = fmaf(m00.x, a0.y, fmaf( m00.y, a0.x, fmaf(m01.x, a1.y,  m01.y * a1.x)));
                        n1.x = fmaf(m10.x, a0.x, fmaf(-m10.y, a0.y, fmaf(m11.x, a1.x, -m11.y * a1.y)));
                        n1.y = fmaf(m10.x, a0.y, fmaf( m10.y, a0.x, fmaf(m11.x, a1.y,  m11.y * a1.x)));
                        s[c] = n0; s[c | (1 << g)] = n1;
                    }
                }
            }

            if (d == DEPTH - 1 && p == 2) {
                // ---- fold final ring + <Z> mean into the reduction ----
                u32 fb = 0;
                #pragma unroll
                for (int j = 0; j < 7; ++j)
                    if ((t >> j) & 1) fb ^= TAB.finv[FILL[2][j]];
                u32 fd[5];
                #pragma unroll
                for (int k = 0; k < 5; ++k) fd[k] = TAB.finv[DIRS[2][k]];
                #pragma unroll
                for (int c = 0; c < 32; ++c) {
                    u32 fv = fb;
                    if (c & 1)  fv ^= fd[0];
                    if (c & 2)  fv ^= fd[1];
                    if (c & 4)  fv ^= fd[2];
                    if (c & 8)  fv ^= fd[3];
                    if (c & 16) fv ^= fd[4];
                    float wgt = (float)(NQ - 2 * __popc(fv));
                    acc = fmaf(fmaf(s[c].x, s[c].x, s[c].y * s[c].y), wgt, acc);
                }
            } else {
                #pragma unroll
                for (int c = 0; c < 32; ++c) {
                    u32 a = pb;
                    if (c & 1)  a ^= qd[0];
                    if (c & 2)  a ^= qd[1];
                    if (c & 4)  a ^= qd[2];
                    if (c & 8)  a ^= qd[3];
                    if (c & 16) a ^= qd[4];
                    sv[a] = s[c];
                }
                __syncthreads();
            }
        }
    }

    // ---- block reduction -> out[bid] ----
    #pragma unroll
    for (int o = 16; o; o >>= 1) acc += __shfl_xor_sync(0xffffffffu, acc, o);
    if ((t & 31) == 0) red[t >> 5] = acc;
    __syncthreads();
    if (t == 0)
        out[bid] = (red[0] + red[1] + red[2] + red[3]) * (1.0f / NQ);
}

extern "C" void kernel_launch(void* const* d_in, const int* in_sizes, int n_in,
                              void* d_out, int out_size)
{
    const float *inp, *wp;
    if (in_sizes[0] == DEPTH * NQ * 3) {            // defensive input-order check
        wp  = (const float*)d_in[0];
        inp = (const float*)d_in[1];
    } else {
        inp = (const float*)d_in[0];
        wp  = (const float*)d_in[1];
    }
    int B = out_size;                                // [B,1] float output
    qsim_kernel<<<B, TPB>>>(inp, wp, (float*)d_out);
}